// round 4
// baseline (speedup 1.0000x reference)
#include <cuda_runtime.h>
#include <math.h>

// ---------------------------------------------------------------------------
// Problem constants
// ---------------------------------------------------------------------------
#define NB      8192
#define ND      64
#define NNEG    128
#define KNBR    32

#define W1c     1e-6f
#define W3c     1e-6f
#define NEG_WEIGHTc 200.0f
#define GAMMAc  1e-4f
#define LAMBDAc 2.5f

#define FULLMASK 0xFFFFFFFFu

// ---------------------------------------------------------------------------
// Scratch (device globals)
// ---------------------------------------------------------------------------
__device__ float g_M[ND * ND];     // M = W_u^T W_i
__device__ float g_cpe[ND];        // W_i^T b_u
__device__ float g_cue[ND];        // W_u^T b_i
__device__ float g_c0;             // b_u . b_i
__device__ float g_norm_partial[NB];
__device__ float g_lossL[NB];
__device__ float g_lossI[NB];
__device__ float g_mseP[NB];
__device__ unsigned g_done;

__device__ __forceinline__ float softplusf(float x) {
    return fmaxf(x, 0.0f) + __logf(1.0f + __expf(-fabsf(x)));
}

__device__ __forceinline__ float bfly(float s) {
    #pragma unroll
    for (int o = 16; o; o >>= 1) s += __shfl_xor_sync(FULLMASK, s, o);
    return s;
}

// ---------------------------------------------------------------------------
// Kernel 1: precompute M = W_u^T W_i (+ bias terms), smem-staged.
// Also resets the last-block counter for this graph replay.
// ---------------------------------------------------------------------------
__global__ void __launch_bounds__(256)
precompute_kernel(const float* __restrict__ wu, const float* __restrict__ bu,
                  const float* __restrict__ wi, const float* __restrict__ bi) {
    __shared__ float swu[ND * ND];
    __shared__ float swi[ND * ND];

    const int tid = threadIdx.x;
    if (blockIdx.x == 0 && tid == 0) g_done = 0u;

    {
        const float4* su = (const float4*)wu;
        const float4* si = (const float4*)wi;
        float4* du = (float4*)swu;
        float4* di = (float4*)swi;
        #pragma unroll
        for (int r = 0; r < 4; r++) {
            du[tid + r * 256] = su[tid + r * 256];
            di[tid + r * 256] = si[tid + r * 256];
        }
    }
    __syncthreads();

    const int idx = blockIdx.x * 256 + tid;
    const int a = idx >> 6;
    const int c = idx & 63;
    float a0 = 0.f, a1 = 0.f, a2 = 0.f, a3 = 0.f;
    #pragma unroll
    for (int d = 0; d < ND; d += 4) {
        a0 = fmaf(swu[(d + 0) * ND + a], swi[(d + 0) * ND + c], a0);
        a1 = fmaf(swu[(d + 1) * ND + a], swi[(d + 1) * ND + c], a1);
        a2 = fmaf(swu[(d + 2) * ND + a], swi[(d + 2) * ND + c], a2);
        a3 = fmaf(swu[(d + 3) * ND + a], swi[(d + 3) * ND + c], a3);
    }
    g_M[idx] = (a0 + a1) + (a2 + a3);

    if (blockIdx.x == 0 && tid < ND) {
        const int j = tid;
        float c1 = 0.0f, c2 = 0.0f;
        #pragma unroll 8
        for (int d = 0; d < ND; d++) {
            c1 = fmaf(swi[d * ND + j], bu[d], c1);
            c2 = fmaf(swu[d * ND + j], bi[d], c2);
        }
        g_cpe[j] = c1;
        g_cue[j] = c2;
        if (j == 0) {
            float s = 0.0f;
            #pragma unroll 8
            for (int d = 0; d < ND; d++) s = fmaf(bu[d], bi[d], s);
            g_c0 = s;
        }
    }
}

// ---------------------------------------------------------------------------
// Fused kernel args
// ---------------------------------------------------------------------------
struct FusedArgs {
    const int*   users;
    const int*   pos_items;
    const int*   neg_items;
    const float* rpkms;
    const float* user_emb;  long nu;
    const float* item_emb;  long ni;
    const float* beta_uD;
    const float* beta_iD;
    const int*   ii_nbr;
    const float* ii_con;
    const float* sp[8]; int sn[8];
    float* out;
};

// ---------------------------------------------------------------------------
// norm slice: grid-stride sum of squares over both big tables
// ---------------------------------------------------------------------------
__device__ __forceinline__ float norm_slice(const FusedArgs& a) {
    float acc = 0.0f;
    const size_t tg = (size_t)blockIdx.x * 256 + threadIdx.x;
    const size_t stride = (size_t)gridDim.x * 256;

    const float4* pu = (const float4*)a.user_emb;
    const size_t mu = (size_t)a.nu >> 2;
    for (size_t i = tg; i < mu; i += stride) {
        float4 v = pu[i];
        acc += v.x*v.x + v.y*v.y + v.z*v.z + v.w*v.w;
    }
    const float4* pi = (const float4*)a.item_emb;
    const size_t mi = (size_t)a.ni >> 2;
    for (size_t i = tg; i < mi; i += stride) {
        float4 v = pi[i];
        acc += v.x*v.x + v.y*v.y + v.z*v.z + v.w*v.w;
    }
    if (blockIdx.x == 0) {
        #pragma unroll
        for (int j = 0; j < 8; j++) {
            const float* q = a.sp[j];
            const int n = a.sn[j];
            for (int i = threadIdx.x; i < n; i += 256) {
                float v = q[i];
                acc += v * v;
            }
        }
    }
    return acc;
}

// ---------------------------------------------------------------------------
// per-sample work (one CTA = one sample).
// ---------------------------------------------------------------------------
__device__ __forceinline__ void sample_work(
    const FusedArgs& a, int b, int u, int p,
    const float* s_ue, const float* s_pe, float* s_t,
    float* sN, float* sI, float* sPosLoss, float* sMse)
{
    const int tid  = threadIdx.x;
    const int lane = tid & 31;
    const int warp = tid >> 5;

    const float  bu  = __ldg(a.beta_uD + u);
    const float2 uev = make_float2(s_ue[2 * lane], s_ue[2 * lane + 1]);

    // ---- coalesced index prefetch: 16 neg idx + 4 nbr idx + 4 sims ----
    const int*   negb = a.neg_items + (size_t)b * NNEG + warp * 16;
    const int*   nbrp = a.ii_nbr   + (size_t)p * KNBR + warp * 4;
    const float* simp = a.ii_con   + (size_t)p * KNBR + warp * 4;
    const int   myneg = (lane < 16) ? __ldg(negb + lane) : 0;
    const int   mynbr = (lane < 4)  ? __ldg(nbrp + lane) : 0;
    const float mysim = (lane < 4)  ? __ldg(simp + lane) : 0.0f;

    // ---- negatives: 2 groups of 8, MLP=8 ----
    float accN = 0.0f;
    #pragma unroll
    for (int g = 0; g < 2; g++) {
        float2 v[8];
        float  bi[8];
        float  s[8];
        #pragma unroll
        for (int n = 0; n < 8; n++) {
            const int it = __shfl_sync(FULLMASK, myneg, g * 8 + n);
            v[n]  = __ldg((const float2*)(a.item_emb + (size_t)it * ND) + lane);
            bi[n] = __ldg(a.beta_iD + it);
        }
        #pragma unroll
        for (int n = 0; n < 8; n++) s[n] = fmaf(v[n].x, uev.x, v[n].y * uev.y);
        #pragma unroll
        for (int o = 16; o; o >>= 1) {
            #pragma unroll
            for (int n = 0; n < 8; n++) s[n] += __shfl_xor_sync(FULLMASK, s[n], o);
        }
        #pragma unroll
        for (int n = 0; n < 8; n++)
            accN += fmaf(bu, bi[n], W3c) * softplusf(s[n]);
    }

    // ---- neighbors: 4, MLP=4 ----
    float accI = 0.0f;
    {
        float2 v[4];
        float  s[4];
        #pragma unroll
        for (int k = 0; k < 4; k++) {
            const int it = __shfl_sync(FULLMASK, mynbr, k);
            v[k] = __ldg((const float2*)(a.item_emb + (size_t)it * ND) + lane);
        }
        #pragma unroll
        for (int k = 0; k < 4; k++) s[k] = fmaf(v[k].x, uev.x, v[k].y * uev.y);
        #pragma unroll
        for (int o = 16; o; o >>= 1) {
            #pragma unroll
            for (int k = 0; k < 4; k++) s[k] += __shfl_xor_sync(FULLMASK, s[k], o);
        }
        #pragma unroll
        for (int k = 0; k < 4; k++) {
            const float c = __shfl_sync(FULLMASK, mysim, k);
            accI += c * softplusf(-s[k]);
        }
    }

    if (lane == 0) { sN[warp] = accN; sI[warp] = accI; }

    // ---- matvec t = M^T ue (+cpe) : coalesced over 64 threads ----
    if (tid < ND) {
        float acc = g_cpe[tid];
        #pragma unroll 16
        for (int d = 0; d < ND; d++)
            acc = fmaf(s_ue[d], g_M[d * ND + tid], acc);
        s_t[tid] = acc;
    }

    // ---- positive score (warp 2) ----
    if (warp == 2) {
        const float2 pv = make_float2(s_pe[2 * lane], s_pe[2 * lane + 1]);
        float s = fmaf(pv.x, uev.x, pv.y * uev.y);
        s = bfly(s);
        if (lane == 0) {
            const float bip = __ldg(a.beta_iD + p);
            *sPosLoss = fmaf(bu, bip, W1c) * softplusf(-s);
        }
    }
    __syncthreads();

    // ---- mse (warp 0) ----
    if (warp == 0) {
        float v = s_t[2*lane] * s_pe[2*lane] + s_t[2*lane+1] * s_pe[2*lane+1]
                + g_cue[2*lane] * s_ue[2*lane] + g_cue[2*lane+1] * s_ue[2*lane+1];
        v = bfly(v);
        if (lane == 0) {
            const float pred = v + g_c0;
            const float dlt = pred - __ldg(a.rpkms + b);
            *sMse = dlt * dlt;
        }
    }
    __syncthreads();

    if (tid == 0) {
        float sn = 0.0f, si = 0.0f;
        #pragma unroll
        for (int w = 0; w < 8; w++) { sn += sN[w]; si += sI[w]; }
        g_lossL[b] = *sPosLoss + NEG_WEIGHTc * (sn * (1.0f / NNEG));
        g_lossI[b] = si;
        g_mseP[b]  = *sMse;
    }
}

// ---------------------------------------------------------------------------
// Fused kernel: one CTA per sample + grid-stride norm slice.
// Last CTA performs the deterministic final reduction.
// __launch_bounds__(256, 4): cap regs at 64, keep 4 CTAs/SM.
// ---------------------------------------------------------------------------
__global__ void __launch_bounds__(256, 4)
fused_kernel(FusedArgs a) {
    const int b = blockIdx.x;
    const int tid = threadIdx.x;

    __shared__ float s_ue[ND];
    __shared__ float s_pe[ND];
    __shared__ float s_t[ND];
    __shared__ float sN[8], sI[8];
    __shared__ float sPosLoss, sMse;
    __shared__ float sNorm[8];
    __shared__ bool  sLast;

    const int u = __ldg(a.users + b);
    const int p = __ldg(a.pos_items + b);
    if (tid < ND)          s_ue[tid]      = __ldg(a.user_emb + (size_t)u * ND + tid);
    else if (tid < 2 * ND) s_pe[tid - ND] = __ldg(a.item_emb + (size_t)p * ND + (tid - ND));
    __syncthreads();

    float nacc;
    if (b & 1) {
        nacc = norm_slice(a);
        sample_work(a, b, u, p, s_ue, s_pe, s_t, sN, sI, &sPosLoss, &sMse);
    } else {
        sample_work(a, b, u, p, s_ue, s_pe, s_t, sN, sI, &sPosLoss, &sMse);
        nacc = norm_slice(a);
    }

    nacc = bfly(nacc);
    if ((tid & 31) == 0) sNorm[tid >> 5] = nacc;
    __syncthreads();
    if (tid == 0) {
        float v = 0.0f;
        #pragma unroll
        for (int w = 0; w < 8; w++) v += sNorm[w];
        g_norm_partial[b] = v;
    }

    // ---- last-block finalize ----
    __threadfence();
    if (tid == 0) sLast = (atomicAdd(&g_done, 1u) == (unsigned)(NB - 1));
    __syncthreads();
    if (!sLast) return;
    __threadfence();

    double aL = 0.0, aI = 0.0, aM = 0.0, aN = 0.0;
    for (int i = tid; i < NB; i += 256) {
        aL += (double)g_lossL[i];
        aI += (double)g_lossI[i];
        aM += (double)g_mseP[i];
        aN += (double)g_norm_partial[i];
    }
    __shared__ double rL[256], rI[256], rM[256], rN[256];
    rL[tid] = aL; rI[tid] = aI; rM[tid] = aM; rN[tid] = aN;
    __syncthreads();
    for (int o = 128; o; o >>= 1) {
        if (tid < o) {
            rL[tid] += rL[tid + o];
            rI[tid] += rI[tid + o];
            rM[tid] += rM[tid + o];
            rN[tid] += rN[tid + o];
        }
        __syncthreads();
    }
    if (tid == 0) {
        const double lossL = rL[0] / (double)NB;
        const double lossI = rI[0] * ((double)LAMBDAc / ((double)NB * (double)KNBR));
        const double mse   = rM[0] / (double)NB;
        const double norm  = rN[0] * 0.5 * (double)GAMMAc;
        float* out = a.out;
        out[0] = (float)(lossL + lossI + mse + norm);
        out[1] = (float)lossL;
        out[2] = (float)lossI;
        out[3] = 0.0f;
        out[4] = (float)mse;
        out[5] = (float)norm;
    }
}

// ---------------------------------------------------------------------------
// Launch
// ---------------------------------------------------------------------------
extern "C" void kernel_launch(void* const* d_in, const int* in_sizes, int n_in,
                              void* d_out, int out_size) {
    FusedArgs a;
    a.users     = (const int*)d_in[0];
    a.pos_items = (const int*)d_in[1];
    a.neg_items = (const int*)d_in[2];
    a.rpkms     = (const float*)d_in[3];
    a.user_emb  = (const float*)d_in[4];  a.nu = in_sizes[4];
    a.item_emb  = (const float*)d_in[5];  a.ni = in_sizes[5];
    a.beta_uD   = (const float*)d_in[6];
    a.beta_iD   = (const float*)d_in[7];
    a.ii_nbr    = (const int*)d_in[8];
    a.ii_con    = (const float*)d_in[9];
    const float* mse_u_w = (const float*)d_in[10];
    const float* mse_u_b = (const float*)d_in[11];
    const float* mse_i_w = (const float*)d_in[12];
    const float* mse_i_b = (const float*)d_in[13];
    a.sp[0] = mse_u_w;               a.sn[0] = in_sizes[10];
    a.sp[1] = mse_u_b;               a.sn[1] = in_sizes[11];
    a.sp[2] = mse_i_w;               a.sn[2] = in_sizes[12];
    a.sp[3] = mse_i_b;               a.sn[3] = in_sizes[13];
    a.sp[4] = (const float*)d_in[14]; a.sn[4] = in_sizes[14];
    a.sp[5] = (const float*)d_in[15]; a.sn[5] = in_sizes[15];
    a.sp[6] = (const float*)d_in[16]; a.sn[6] = in_sizes[16];
    a.sp[7] = (const float*)d_in[17]; a.sn[7] = in_sizes[17];
    a.out   = (float*)d_out;

    precompute_kernel<<<16, 256>>>(mse_u_w, mse_u_b, mse_i_w, mse_i_b);
    fused_kernel<<<NB, 256>>>(a);
}

// round 5
// speedup vs baseline: 1.1470x; 1.1470x over previous
#include <cuda_runtime.h>
#include <math.h>

// ---------------------------------------------------------------------------
// Problem constants
// ---------------------------------------------------------------------------
#define NB      8192
#define ND      64
#define NNEG    128
#define KNBR    32

#define W1c     1e-6f
#define W3c     1e-6f
#define NEG_WEIGHTc 200.0f
#define GAMMAc  1e-4f
#define LAMBDAc 2.5f

#define FULLMASK 0xFFFFFFFFu

// ---------------------------------------------------------------------------
// Scratch (device globals)
// ---------------------------------------------------------------------------
__device__ float g_M[ND * ND];     // M = W_u^T W_i
__device__ float g_cpe[ND];        // W_i^T b_u
__device__ float g_cue[ND];        // W_u^T b_i
__device__ float g_c0;             // b_u . b_i
__device__ float g_norm_partial[NB];
__device__ float g_lossL[NB];
__device__ float g_lossI[NB];
__device__ float g_mseP[NB];
__device__ unsigned g_done;

__device__ __forceinline__ float softplusf(float x) {
    return fmaxf(x, 0.0f) + __logf(1.0f + __expf(-fabsf(x)));
}

__device__ __forceinline__ float bfly(float s) {
    #pragma unroll
    for (int o = 16; o; o >>= 1) s += __shfl_xor_sync(FULLMASK, s, o);
    return s;
}

// ---------------------------------------------------------------------------
// Kernel 1: precompute M = W_u^T W_i (+ bias terms), smem-staged.
// Also resets the last-block counter for this graph replay.
// ---------------------------------------------------------------------------
__global__ void __launch_bounds__(256)
precompute_kernel(const float* __restrict__ wu, const float* __restrict__ bu,
                  const float* __restrict__ wi, const float* __restrict__ bi) {
    __shared__ float swu[ND * ND];
    __shared__ float swi[ND * ND];

    const int tid = threadIdx.x;
    if (blockIdx.x == 0 && tid == 0) g_done = 0u;

    {
        const float4* su = (const float4*)wu;
        const float4* si = (const float4*)wi;
        float4* du = (float4*)swu;
        float4* di = (float4*)swi;
        #pragma unroll
        for (int r = 0; r < 4; r++) {
            du[tid + r * 256] = su[tid + r * 256];
            di[tid + r * 256] = si[tid + r * 256];
        }
    }
    __syncthreads();

    const int idx = blockIdx.x * 256 + tid;
    const int a = idx >> 6;
    const int c = idx & 63;
    float a0 = 0.f, a1 = 0.f, a2 = 0.f, a3 = 0.f;
    #pragma unroll
    for (int d = 0; d < ND; d += 4) {
        a0 = fmaf(swu[(d + 0) * ND + a], swi[(d + 0) * ND + c], a0);
        a1 = fmaf(swu[(d + 1) * ND + a], swi[(d + 1) * ND + c], a1);
        a2 = fmaf(swu[(d + 2) * ND + a], swi[(d + 2) * ND + c], a2);
        a3 = fmaf(swu[(d + 3) * ND + a], swi[(d + 3) * ND + c], a3);
    }
    g_M[idx] = (a0 + a1) + (a2 + a3);

    if (blockIdx.x == 0 && tid < ND) {
        const int j = tid;
        float c1 = 0.0f, c2 = 0.0f;
        #pragma unroll 8
        for (int d = 0; d < ND; d++) {
            c1 = fmaf(swi[d * ND + j], bu[d], c1);
            c2 = fmaf(swu[d * ND + j], bi[d], c2);
        }
        g_cpe[j] = c1;
        g_cue[j] = c2;
        if (j == 0) {
            float s = 0.0f;
            #pragma unroll 8
            for (int d = 0; d < ND; d++) s = fmaf(bu[d], bi[d], s);
            g_c0 = s;
        }
    }
}

// ---------------------------------------------------------------------------
// Fused kernel args
// ---------------------------------------------------------------------------
struct FusedArgs {
    const int*   users;
    const int*   pos_items;
    const int*   neg_items;
    const float* rpkms;
    const float* user_emb;  long nu;
    const float* item_emb;  long ni;
    const float* beta_uD;
    const float* beta_iD;
    const int*   ii_nbr;
    const float* ii_con;
    const float* sp[8]; int sn[8];
    float* out;
};

// ---------------------------------------------------------------------------
// norm slice: grid-stride sum of squares over both big tables.
// Loads use __ldcs (evict-first) so the once-read 256 MB stream does NOT
// evict gather-resident item rows from L2.
// ---------------------------------------------------------------------------
__device__ __forceinline__ float norm_slice(const FusedArgs& a) {
    float acc = 0.0f;
    const size_t tg = (size_t)blockIdx.x * 256 + threadIdx.x;
    const size_t stride = (size_t)gridDim.x * 256;

    const float4* pu = (const float4*)a.user_emb;
    const size_t mu = (size_t)a.nu >> 2;
    for (size_t i = tg; i < mu; i += stride) {
        float4 v = __ldcs(pu + i);
        acc += v.x*v.x + v.y*v.y + v.z*v.z + v.w*v.w;
    }
    const float4* pi = (const float4*)a.item_emb;
    const size_t mi = (size_t)a.ni >> 2;
    for (size_t i = tg; i < mi; i += stride) {
        float4 v = __ldcs(pi + i);
        acc += v.x*v.x + v.y*v.y + v.z*v.z + v.w*v.w;
    }
    if (blockIdx.x == 0) {
        #pragma unroll
        for (int j = 0; j < 8; j++) {
            const float* q = a.sp[j];
            const int n = a.sn[j];
            for (int i = threadIdx.x; i < n; i += 256) {
                float v = q[i];
                acc += v * v;
            }
        }
    }
    return acc;
}

// ---------------------------------------------------------------------------
// per-sample work (one CTA = one sample).
// ---------------------------------------------------------------------------
__device__ __forceinline__ void sample_work(
    const FusedArgs& a, int b, int u, int p,
    const float* s_ue, const float* s_pe, float* s_t,
    float* sN, float* sI, float* sPosLoss, float* sMse)
{
    const int tid  = threadIdx.x;
    const int lane = tid & 31;
    const int warp = tid >> 5;

    const float  bu  = __ldg(a.beta_uD + u);
    const float2 uev = make_float2(s_ue[2 * lane], s_ue[2 * lane + 1]);

    // ---- coalesced index prefetch: 16 neg idx + 4 nbr idx + 4 sims ----
    const int*   negb = a.neg_items + (size_t)b * NNEG + warp * 16;
    const int*   nbrp = a.ii_nbr   + (size_t)p * KNBR + warp * 4;
    const float* simp = a.ii_con   + (size_t)p * KNBR + warp * 4;
    const int   myneg = (lane < 16) ? __ldg(negb + lane) : 0;
    const int   mynbr = (lane < 4)  ? __ldg(nbrp + lane) : 0;
    const float mysim = (lane < 4)  ? __ldg(simp + lane) : 0.0f;

    // ---- negatives: 4 groups of 4, MLP=4 ----
    float accN = 0.0f;
    #pragma unroll
    for (int g = 0; g < 4; g++) {
        float2 v[4];
        float  bi[4];
        float  s[4];
        #pragma unroll
        for (int n = 0; n < 4; n++) {
            const int it = __shfl_sync(FULLMASK, myneg, g * 4 + n);
            v[n]  = __ldg((const float2*)(a.item_emb + (size_t)it * ND) + lane);
            bi[n] = __ldg(a.beta_iD + it);
        }
        #pragma unroll
        for (int n = 0; n < 4; n++) s[n] = fmaf(v[n].x, uev.x, v[n].y * uev.y);
        #pragma unroll
        for (int o = 16; o; o >>= 1) {
            #pragma unroll
            for (int n = 0; n < 4; n++) s[n] += __shfl_xor_sync(FULLMASK, s[n], o);
        }
        #pragma unroll
        for (int n = 0; n < 4; n++)
            accN += fmaf(bu, bi[n], W3c) * softplusf(s[n]);
    }

    // ---- neighbors: 4, MLP=4 ----
    float accI = 0.0f;
    {
        float2 v[4];
        float  s[4];
        #pragma unroll
        for (int k = 0; k < 4; k++) {
            const int it = __shfl_sync(FULLMASK, mynbr, k);
            v[k] = __ldg((const float2*)(a.item_emb + (size_t)it * ND) + lane);
        }
        #pragma unroll
        for (int k = 0; k < 4; k++) s[k] = fmaf(v[k].x, uev.x, v[k].y * uev.y);
        #pragma unroll
        for (int o = 16; o; o >>= 1) {
            #pragma unroll
            for (int k = 0; k < 4; k++) s[k] += __shfl_xor_sync(FULLMASK, s[k], o);
        }
        #pragma unroll
        for (int k = 0; k < 4; k++) {
            const float c = __shfl_sync(FULLMASK, mysim, k);
            accI += c * softplusf(-s[k]);
        }
    }

    if (lane == 0) { sN[warp] = accN; sI[warp] = accI; }

    // ---- matvec t = M^T ue (+cpe) : coalesced over 64 threads ----
    if (tid < ND) {
        float acc = g_cpe[tid];
        #pragma unroll 16
        for (int d = 0; d < ND; d++)
            acc = fmaf(s_ue[d], g_M[d * ND + tid], acc);
        s_t[tid] = acc;
    }

    // ---- positive score (warp 2) ----
    if (warp == 2) {
        const float2 pv = make_float2(s_pe[2 * lane], s_pe[2 * lane + 1]);
        float s = fmaf(pv.x, uev.x, pv.y * uev.y);
        s = bfly(s);
        if (lane == 0) {
            const float bip = __ldg(a.beta_iD + p);
            *sPosLoss = fmaf(bu, bip, W1c) * softplusf(-s);
        }
    }
    __syncthreads();

    // ---- mse (warp 0) ----
    if (warp == 0) {
        float v = s_t[2*lane] * s_pe[2*lane] + s_t[2*lane+1] * s_pe[2*lane+1]
                + g_cue[2*lane] * s_ue[2*lane] + g_cue[2*lane+1] * s_ue[2*lane+1];
        v = bfly(v);
        if (lane == 0) {
            const float pred = v + g_c0;
            const float dlt = pred - __ldg(a.rpkms + b);
            *sMse = dlt * dlt;
        }
    }
    __syncthreads();

    if (tid == 0) {
        float sn = 0.0f, si = 0.0f;
        #pragma unroll
        for (int w = 0; w < 8; w++) { sn += sN[w]; si += sI[w]; }
        g_lossL[b] = *sPosLoss + NEG_WEIGHTc * (sn * (1.0f / NNEG));
        g_lossI[b] = si;
        g_mseP[b]  = *sMse;
    }
}

// ---------------------------------------------------------------------------
// Fused kernel: one CTA per sample + grid-stride norm slice.
// Last CTA performs the deterministic final reduction.
// ---------------------------------------------------------------------------
__global__ void __launch_bounds__(256, 5)
fused_kernel(FusedArgs a) {
    const int b = blockIdx.x;
    const int tid = threadIdx.x;

    __shared__ float s_ue[ND];
    __shared__ float s_pe[ND];
    __shared__ float s_t[ND];
    __shared__ float sN[8], sI[8];
    __shared__ float sPosLoss, sMse;
    __shared__ float sNorm[8];
    __shared__ bool  sLast;

    const int u = __ldg(a.users + b);
    const int p = __ldg(a.pos_items + b);
    if (tid < ND)          s_ue[tid]      = __ldg(a.user_emb + (size_t)u * ND + tid);
    else if (tid < 2 * ND) s_pe[tid - ND] = __ldg(a.item_emb + (size_t)p * ND + (tid - ND));
    __syncthreads();

    float nacc;
    if (b & 1) {
        nacc = norm_slice(a);
        sample_work(a, b, u, p, s_ue, s_pe, s_t, sN, sI, &sPosLoss, &sMse);
    } else {
        sample_work(a, b, u, p, s_ue, s_pe, s_t, sN, sI, &sPosLoss, &sMse);
        nacc = norm_slice(a);
    }

    nacc = bfly(nacc);
    if ((tid & 31) == 0) sNorm[tid >> 5] = nacc;
    __syncthreads();
    if (tid == 0) {
        float v = 0.0f;
        #pragma unroll
        for (int w = 0; w < 8; w++) v += sNorm[w];
        g_norm_partial[b] = v;
    }

    // ---- last-block finalize ----
    __threadfence();
    if (tid == 0) sLast = (atomicAdd(&g_done, 1u) == (unsigned)(NB - 1));
    __syncthreads();
    if (!sLast) return;
    __threadfence();

    double aL = 0.0, aI = 0.0, aM = 0.0, aN = 0.0;
    for (int i = tid; i < NB; i += 256) {
        aL += (double)g_lossL[i];
        aI += (double)g_lossI[i];
        aM += (double)g_mseP[i];
        aN += (double)g_norm_partial[i];
    }
    __shared__ double rL[256], rI[256], rM[256], rN[256];
    rL[tid] = aL; rI[tid] = aI; rM[tid] = aM; rN[tid] = aN;
    __syncthreads();
    for (int o = 128; o; o >>= 1) {
        if (tid < o) {
            rL[tid] += rL[tid + o];
            rI[tid] += rI[tid + o];
            rM[tid] += rM[tid + o];
            rN[tid] += rN[tid + o];
        }
        __syncthreads();
    }
    if (tid == 0) {
        const double lossL = rL[0] / (double)NB;
        const double lossI = rI[0] * ((double)LAMBDAc / ((double)NB * (double)KNBR));
        const double mse   = rM[0] / (double)NB;
        const double norm  = rN[0] * 0.5 * (double)GAMMAc;
        float* out = a.out;
        out[0] = (float)(lossL + lossI + mse + norm);
        out[1] = (float)lossL;
        out[2] = (float)lossI;
        out[3] = 0.0f;
        out[4] = (float)mse;
        out[5] = (float)norm;
    }
}

// ---------------------------------------------------------------------------
// Launch
// ---------------------------------------------------------------------------
extern "C" void kernel_launch(void* const* d_in, const int* in_sizes, int n_in,
                              void* d_out, int out_size) {
    FusedArgs a;
    a.users     = (const int*)d_in[0];
    a.pos_items = (const int*)d_in[1];
    a.neg_items = (const int*)d_in[2];
    a.rpkms     = (const float*)d_in[3];
    a.user_emb  = (const float*)d_in[4];  a.nu = in_sizes[4];
    a.item_emb  = (const float*)d_in[5];  a.ni = in_sizes[5];
    a.beta_uD   = (const float*)d_in[6];
    a.beta_iD   = (const float*)d_in[7];
    a.ii_nbr    = (const int*)d_in[8];
    a.ii_con    = (const float*)d_in[9];
    const float* mse_u_w = (const float*)d_in[10];
    const float* mse_u_b = (const float*)d_in[11];
    const float* mse_i_w = (const float*)d_in[12];
    const float* mse_i_b = (const float*)d_in[13];
    a.sp[0] = mse_u_w;               a.sn[0] = in_sizes[10];
    a.sp[1] = mse_u_b;               a.sn[1] = in_sizes[11];
    a.sp[2] = mse_i_w;               a.sn[2] = in_sizes[12];
    a.sp[3] = mse_i_b;               a.sn[3] = in_sizes[13];
    a.sp[4] = (const float*)d_in[14]; a.sn[4] = in_sizes[14];
    a.sp[5] = (const float*)d_in[15]; a.sn[5] = in_sizes[15];
    a.sp[6] = (const float*)d_in[16]; a.sn[6] = in_sizes[16];
    a.sp[7] = (const float*)d_in[17]; a.sn[7] = in_sizes[17];
    a.out   = (float*)d_out;

    precompute_kernel<<<16, 256>>>(mse_u_w, mse_u_b, mse_i_w, mse_i_b);
    fused_kernel<<<NB, 256>>>(a);
}

// round 6
// speedup vs baseline: 1.2000x; 1.0462x over previous
#include <cuda_runtime.h>
#include <math.h>

// ---------------------------------------------------------------------------
// Problem constants
// ---------------------------------------------------------------------------
#define NB      8192
#define ND      64
#define NNEG    128
#define KNBR    32

#define W1c     1e-6f
#define W3c     1e-6f
#define NEG_WEIGHTc 200.0f
#define GAMMAc  1e-4f
#define LAMBDAc 2.5f

#define FULLMASK 0xFFFFFFFFu

// ---------------------------------------------------------------------------
// Scratch (device globals)
// ---------------------------------------------------------------------------
__device__ float g_M[ND * ND];     // M = W_u^T W_i
__device__ float g_cpe[ND];        // W_i^T b_u
__device__ float g_cue[ND];        // W_u^T b_i
__device__ float g_c0;             // b_u . b_i
__device__ float g_norm_partial[NB];
__device__ float g_lossL[NB];
__device__ float g_lossI[NB];
__device__ float g_mseP[NB];
__device__ unsigned g_done;

__device__ __forceinline__ float softplusf(float x) {
    return fmaxf(x, 0.0f) + __logf(1.0f + __expf(-fabsf(x)));
}

__device__ __forceinline__ float bfly(float s) {
    #pragma unroll
    for (int o = 16; o; o >>= 1) s += __shfl_xor_sync(FULLMASK, s, o);
    return s;
}

__device__ __forceinline__ float dot8(float4 va, float4 vb, float4 ua, float4 ub) {
    float s = va.x * ua.x;
    s = fmaf(va.y, ua.y, s);
    s = fmaf(va.z, ua.z, s);
    s = fmaf(va.w, ua.w, s);
    s = fmaf(vb.x, ub.x, s);
    s = fmaf(vb.y, ub.y, s);
    s = fmaf(vb.z, ub.z, s);
    s = fmaf(vb.w, ub.w, s);
    return s;
}

// ---------------------------------------------------------------------------
// Kernel 1: precompute M = W_u^T W_i (+ bias terms), smem-staged.
// Also resets the last-block counter for this graph replay.
// ---------------------------------------------------------------------------
__global__ void __launch_bounds__(256)
precompute_kernel(const float* __restrict__ wu, const float* __restrict__ bu,
                  const float* __restrict__ wi, const float* __restrict__ bi) {
    __shared__ float swu[ND * ND];
    __shared__ float swi[ND * ND];

    const int tid = threadIdx.x;
    if (blockIdx.x == 0 && tid == 0) g_done = 0u;

    {
        const float4* su = (const float4*)wu;
        const float4* si = (const float4*)wi;
        float4* du = (float4*)swu;
        float4* di = (float4*)swi;
        #pragma unroll
        for (int r = 0; r < 4; r++) {
            du[tid + r * 256] = su[tid + r * 256];
            di[tid + r * 256] = si[tid + r * 256];
        }
    }
    __syncthreads();

    const int idx = blockIdx.x * 256 + tid;
    const int a = idx >> 6;
    const int c = idx & 63;
    float a0 = 0.f, a1 = 0.f, a2 = 0.f, a3 = 0.f;
    #pragma unroll
    for (int d = 0; d < ND; d += 4) {
        a0 = fmaf(swu[(d + 0) * ND + a], swi[(d + 0) * ND + c], a0);
        a1 = fmaf(swu[(d + 1) * ND + a], swi[(d + 1) * ND + c], a1);
        a2 = fmaf(swu[(d + 2) * ND + a], swi[(d + 2) * ND + c], a2);
        a3 = fmaf(swu[(d + 3) * ND + a], swi[(d + 3) * ND + c], a3);
    }
    g_M[idx] = (a0 + a1) + (a2 + a3);

    if (blockIdx.x == 0 && tid < ND) {
        const int j = tid;
        float c1 = 0.0f, c2 = 0.0f;
        #pragma unroll 8
        for (int d = 0; d < ND; d++) {
            c1 = fmaf(swi[d * ND + j], bu[d], c1);
            c2 = fmaf(swu[d * ND + j], bi[d], c2);
        }
        g_cpe[j] = c1;
        g_cue[j] = c2;
        if (j == 0) {
            float s = 0.0f;
            #pragma unroll 8
            for (int d = 0; d < ND; d++) s = fmaf(bu[d], bi[d], s);
            g_c0 = s;
        }
    }
}

// ---------------------------------------------------------------------------
// Fused kernel args
// ---------------------------------------------------------------------------
struct FusedArgs {
    const int*   users;
    const int*   pos_items;
    const int*   neg_items;
    const float* rpkms;
    const float* user_emb;  long nu;
    const float* item_emb;  long ni;
    const float* beta_uD;
    const float* beta_iD;
    const int*   ii_nbr;
    const float* ii_con;
    const float* sp[8]; int sn[8];
    float* out;
};

// ---------------------------------------------------------------------------
// norm slice: grid-stride sum of squares, __ldcs (evict-first), 2-way unroll
// ---------------------------------------------------------------------------
__device__ __forceinline__ float norm_slice(const FusedArgs& a) {
    float acc0 = 0.0f, acc1 = 0.0f;
    const size_t tg = (size_t)blockIdx.x * 256 + threadIdx.x;
    const size_t stride = (size_t)gridDim.x * 256;

    const float4* pu = (const float4*)a.user_emb;
    const size_t mu = (size_t)a.nu >> 2;
    size_t i = tg;
    for (; i + stride < mu; i += 2 * stride) {
        float4 v0 = __ldcs(pu + i);
        float4 v1 = __ldcs(pu + i + stride);
        acc0 += v0.x*v0.x + v0.y*v0.y + v0.z*v0.z + v0.w*v0.w;
        acc1 += v1.x*v1.x + v1.y*v1.y + v1.z*v1.z + v1.w*v1.w;
    }
    for (; i < mu; i += stride) {
        float4 v = __ldcs(pu + i);
        acc0 += v.x*v.x + v.y*v.y + v.z*v.z + v.w*v.w;
    }
    const float4* pi = (const float4*)a.item_emb;
    const size_t mi = (size_t)a.ni >> 2;
    i = tg;
    for (; i + stride < mi; i += 2 * stride) {
        float4 v0 = __ldcs(pi + i);
        float4 v1 = __ldcs(pi + i + stride);
        acc0 += v0.x*v0.x + v0.y*v0.y + v0.z*v0.z + v0.w*v0.w;
        acc1 += v1.x*v1.x + v1.y*v1.y + v1.z*v1.z + v1.w*v1.w;
    }
    for (; i < mi; i += stride) {
        float4 v = __ldcs(pi + i);
        acc0 += v.x*v.x + v.y*v.y + v.z*v.z + v.w*v.w;
    }
    if (blockIdx.x == 0) {
        #pragma unroll
        for (int j = 0; j < 8; j++) {
            const float* q = a.sp[j];
            const int n = a.sn[j];
            for (int k = threadIdx.x; k < n; k += 256) {
                float v = q[k];
                acc0 += v * v;
            }
        }
    }
    return acc0 + acc1;
}

// ---------------------------------------------------------------------------
// per-sample work (one CTA = one sample).
// Dot geometry: 8 lanes per item row, 4 rows per warp slot, 3-stage reduce.
// ---------------------------------------------------------------------------
__device__ __forceinline__ void sample_work(
    const FusedArgs& a, int b, int u, int p,
    const float* s_ue, const float* s_pe, float* s_t,
    float* sN, float* sI, float* sPosLoss, float* sMse)
{
    const int tid   = threadIdx.x;
    const int lane  = tid & 31;
    const int warp  = tid >> 5;
    const int lane8 = lane & 7;     // position within 8-lane group
    const int grp   = lane >> 3;    // 0..3: which row in the slot

    const float bu = __ldg(a.beta_uD + u);

    // per-lane ue fragment (dims [lane8*4, +4) and [32+lane8*4, +4))
    const float4 ua = ((const float4*)s_ue)[lane8];
    const float4 ub = ((const float4*)s_ue)[8 + lane8];

    // ---- coalesced prefetch: 16 neg idx + betas, 4 nbr idx + sims ----
    const int*   negb = a.neg_items + (size_t)b * NNEG + warp * 16;
    const int*   nbrp = a.ii_nbr   + (size_t)p * KNBR + warp * 4;
    const float* simp = a.ii_con   + (size_t)p * KNBR + warp * 4;
    const int   myneg = (lane < 16) ? __ldg(negb + lane) : 0;
    const float mybi  = (lane < 16) ? __ldg(a.beta_iD + myneg) : 0.0f;
    const int   mynbr = (lane < 4)  ? __ldg(nbrp + lane) : 0;
    const float mysim = (lane < 4)  ? __ldg(simp + lane) : 0.0f;

    // ---- negatives: 4 slots x 4 rows, 8 lanes per row ----
    float accN = 0.0f;
    #pragma unroll
    for (int slot = 0; slot < 4; slot++) {
        const int j = __shfl_sync(FULLMASK, myneg, slot * 4 + grp);
        const float4* row = (const float4*)(a.item_emb + (size_t)j * ND);
        const float4 va = __ldg(row + lane8);
        const float4 vb = __ldg(row + 8 + lane8);
        float s = dot8(va, vb, ua, ub);
        s += __shfl_xor_sync(FULLMASK, s, 1);
        s += __shfl_xor_sync(FULLMASK, s, 2);
        s += __shfl_xor_sync(FULLMASK, s, 4);
        const float bi = __shfl_sync(FULLMASK, mybi, slot * 4 + grp);
        if (lane8 == 0)
            accN += fmaf(bu, bi, W3c) * softplusf(s);
    }

    // ---- neighbors: one slot of 4 rows ----
    float accI = 0.0f;
    {
        const int j = __shfl_sync(FULLMASK, mynbr, grp);
        const float4* row = (const float4*)(a.item_emb + (size_t)j * ND);
        const float4 va = __ldg(row + lane8);
        const float4 vb = __ldg(row + 8 + lane8);
        float s = dot8(va, vb, ua, ub);
        s += __shfl_xor_sync(FULLMASK, s, 1);
        s += __shfl_xor_sync(FULLMASK, s, 2);
        s += __shfl_xor_sync(FULLMASK, s, 4);
        const float c = __shfl_sync(FULLMASK, mysim, grp);
        if (lane8 == 0)
            accI = c * softplusf(-s);
    }

    // full-warp reduce of the group-leader partials
    accN = bfly(accN);
    accI = bfly(accI);
    if (lane == 0) { sN[warp] = accN; sI[warp] = accI; }

    // ---- matvec t = M^T ue (+cpe) : coalesced over 64 threads ----
    if (tid < ND) {
        float acc = g_cpe[tid];
        #pragma unroll 16
        for (int d = 0; d < ND; d++)
            acc = fmaf(s_ue[d], g_M[d * ND + tid], acc);
        s_t[tid] = acc;
    }

    // ---- positive score (warp 2): 8-lane group geometry on pe ----
    if (warp == 2) {
        const float4* prow = (const float4*)s_pe;
        // all 4 groups compute the same dot (pe fixed) — use group 0 result
        const float4 pa = prow[lane8];
        const float4 pb = prow[8 + lane8];
        float s = dot8(pa, pb, ua, ub);
        s += __shfl_xor_sync(FULLMASK, s, 1);
        s += __shfl_xor_sync(FULLMASK, s, 2);
        s += __shfl_xor_sync(FULLMASK, s, 4);
        if (lane == 0) {
            const float bip = __ldg(a.beta_iD + p);
            *sPosLoss = fmaf(bu, bip, W1c) * softplusf(-s);
        }
    }
    __syncthreads();

    // ---- mse (warp 0) ----
    if (warp == 0) {
        float v = s_t[2*lane] * s_pe[2*lane] + s_t[2*lane+1] * s_pe[2*lane+1]
                + g_cue[2*lane] * s_ue[2*lane] + g_cue[2*lane+1] * s_ue[2*lane+1];
        v = bfly(v);
        if (lane == 0) {
            const float pred = v + g_c0;
            const float dlt = pred - __ldg(a.rpkms + b);
            *sMse = dlt * dlt;
        }
    }
    __syncthreads();

    if (tid == 0) {
        float sn = 0.0f, si = 0.0f;
        #pragma unroll
        for (int w = 0; w < 8; w++) { sn += sN[w]; si += sI[w]; }
        g_lossL[b] = *sPosLoss + NEG_WEIGHTc * (sn * (1.0f / NNEG));
        g_lossI[b] = si;
        g_mseP[b]  = *sMse;
    }
}

// ---------------------------------------------------------------------------
// Fused kernel: one CTA per sample + grid-stride norm slice.
// Last CTA performs the deterministic final reduction.
// ---------------------------------------------------------------------------
__global__ void __launch_bounds__(256, 5)
fused_kernel(FusedArgs a) {
    const int b = blockIdx.x;
    const int tid = threadIdx.x;

    __shared__ float s_ue[ND];
    __shared__ float s_pe[ND];
    __shared__ float s_t[ND];
    __shared__ float sN[8], sI[8];
    __shared__ float sPosLoss, sMse;
    __shared__ float sNorm[8];
    __shared__ bool  sLast;

    const int u = __ldg(a.users + b);
    const int p = __ldg(a.pos_items + b);
    if (tid < ND)          s_ue[tid]      = __ldg(a.user_emb + (size_t)u * ND + tid);
    else if (tid < 2 * ND) s_pe[tid - ND] = __ldg(a.item_emb + (size_t)p * ND + (tid - ND));
    __syncthreads();

    float nacc;
    if (b & 1) {
        nacc = norm_slice(a);
        sample_work(a, b, u, p, s_ue, s_pe, s_t, sN, sI, &sPosLoss, &sMse);
    } else {
        sample_work(a, b, u, p, s_ue, s_pe, s_t, sN, sI, &sPosLoss, &sMse);
        nacc = norm_slice(a);
    }

    nacc = bfly(nacc);
    if ((tid & 31) == 0) sNorm[tid >> 5] = nacc;
    __syncthreads();
    if (tid == 0) {
        float v = 0.0f;
        #pragma unroll
        for (int w = 0; w < 8; w++) v += sNorm[w];
        g_norm_partial[b] = v;
    }

    // ---- last-block finalize ----
    __threadfence();
    if (tid == 0) sLast = (atomicAdd(&g_done, 1u) == (unsigned)(NB - 1));
    __syncthreads();
    if (!sLast) return;
    __threadfence();

    double aL = 0.0, aI = 0.0, aM = 0.0, aN = 0.0;
    for (int i = tid; i < NB; i += 256) {
        aL += (double)g_lossL[i];
        aI += (double)g_lossI[i];
        aM += (double)g_mseP[i];
        aN += (double)g_norm_partial[i];
    }
    __shared__ double rL[256], rI[256], rM[256], rN[256];
    rL[tid] = aL; rI[tid] = aI; rM[tid] = aM; rN[tid] = aN;
    __syncthreads();
    for (int o = 128; o; o >>= 1) {
        if (tid < o) {
            rL[tid] += rL[tid + o];
            rI[tid] += rI[tid + o];
            rM[tid] += rM[tid + o];
            rN[tid] += rN[tid + o];
        }
        __syncthreads();
    }
    if (tid == 0) {
        const double lossL = rL[0] / (double)NB;
        const double lossI = rI[0] * ((double)LAMBDAc / ((double)NB * (double)KNBR));
        const double mse   = rM[0] / (double)NB;
        const double norm  = rN[0] * 0.5 * (double)GAMMAc;
        float* out = a.out;
        out[0] = (float)(lossL + lossI + mse + norm);
        out[1] = (float)lossL;
        out[2] = (float)lossI;
        out[3] = 0.0f;
        out[4] = (float)mse;
        out[5] = (float)norm;
    }
}

// ---------------------------------------------------------------------------
// Launch
// ---------------------------------------------------------------------------
extern "C" void kernel_launch(void* const* d_in, const int* in_sizes, int n_in,
                              void* d_out, int out_size) {
    FusedArgs a;
    a.users     = (const int*)d_in[0];
    a.pos_items = (const int*)d_in[1];
    a.neg_items = (const int*)d_in[2];
    a.rpkms     = (const float*)d_in[3];
    a.user_emb  = (const float*)d_in[4];  a.nu = in_sizes[4];
    a.item_emb  = (const float*)d_in[5];  a.ni = in_sizes[5];
    a.beta_uD   = (const float*)d_in[6];
    a.beta_iD   = (const float*)d_in[7];
    a.ii_nbr    = (const int*)d_in[8];
    a.ii_con    = (const float*)d_in[9];
    const float* mse_u_w = (const float*)d_in[10];
    const float* mse_u_b = (const float*)d_in[11];
    const float* mse_i_w = (const float*)d_in[12];
    const float* mse_i_b = (const float*)d_in[13];
    a.sp[0] = mse_u_w;               a.sn[0] = in_sizes[10];
    a.sp[1] = mse_u_b;               a.sn[1] = in_sizes[11];
    a.sp[2] = mse_i_w;               a.sn[2] = in_sizes[12];
    a.sp[3] = mse_i_b;               a.sn[3] = in_sizes[13];
    a.sp[4] = (const float*)d_in[14]; a.sn[4] = in_sizes[14];
    a.sp[5] = (const float*)d_in[15]; a.sn[5] = in_sizes[15];
    a.sp[6] = (const float*)d_in[16]; a.sn[6] = in_sizes[16];
    a.sp[7] = (const float*)d_in[17]; a.sn[7] = in_sizes[17];
    a.out   = (float*)d_out;

    precompute_kernel<<<16, 256>>>(mse_u_w, mse_u_b, mse_i_w, mse_i_b);
    fused_kernel<<<NB, 256>>>(a);
}

// round 7
// speedup vs baseline: 1.2561x; 1.0467x over previous
#include <cuda_runtime.h>
#include <math.h>

// ---------------------------------------------------------------------------
// Problem constants
// ---------------------------------------------------------------------------
#define NB      8192
#define ND      64
#define NNEG    128
#define KNBR    32

#define W1c     1e-6f
#define W3c     1e-6f
#define NEG_WEIGHTc 200.0f
#define GAMMAc  1e-4f
#define LAMBDAc 2.5f

#define FULLMASK 0xFFFFFFFFu

// ---------------------------------------------------------------------------
// Scratch (device globals)
// ---------------------------------------------------------------------------
__device__ float g_M[ND * ND];     // M = W_u^T W_i
__device__ float g_cpe[ND];        // W_i^T b_u
__device__ float g_cue[ND];        // W_u^T b_i
__device__ float g_c0;             // b_u . b_i
__device__ float g_norm_partial[NB];
__device__ float g_lossL[NB];
__device__ float g_lossI[NB];
__device__ float g_mseP[NB];
__device__ unsigned g_done;

__device__ __forceinline__ float softplusf(float x) {
    return fmaxf(x, 0.0f) + __logf(1.0f + __expf(-fabsf(x)));
}

__device__ __forceinline__ float bfly(float s) {
    #pragma unroll
    for (int o = 16; o; o >>= 1) s += __shfl_xor_sync(FULLMASK, s, o);
    return s;
}

__device__ __forceinline__ float dot8(float4 va, float4 vb, float4 ua, float4 ub) {
    float s = va.x * ua.x;
    s = fmaf(va.y, ua.y, s);
    s = fmaf(va.z, ua.z, s);
    s = fmaf(va.w, ua.w, s);
    s = fmaf(vb.x, ub.x, s);
    s = fmaf(vb.y, ub.y, s);
    s = fmaf(vb.z, ub.z, s);
    s = fmaf(vb.w, ub.w, s);
    return s;
}

#define BAR_GATHER() asm volatile("bar.sync 1, 128;" ::: "memory")

// ---------------------------------------------------------------------------
// Kernel 1: precompute M = W_u^T W_i (+ bias terms), smem-staged.
// Also resets the last-block counter for this graph replay.
// ---------------------------------------------------------------------------
__global__ void __launch_bounds__(256)
precompute_kernel(const float* __restrict__ wu, const float* __restrict__ bu,
                  const float* __restrict__ wi, const float* __restrict__ bi) {
    __shared__ float swu[ND * ND];
    __shared__ float swi[ND * ND];

    const int tid = threadIdx.x;
    if (blockIdx.x == 0 && tid == 0) g_done = 0u;

    {
        const float4* su = (const float4*)wu;
        const float4* si = (const float4*)wi;
        float4* du = (float4*)swu;
        float4* di = (float4*)swi;
        #pragma unroll
        for (int r = 0; r < 4; r++) {
            du[tid + r * 256] = su[tid + r * 256];
            di[tid + r * 256] = si[tid + r * 256];
        }
    }
    __syncthreads();

    const int idx = blockIdx.x * 256 + tid;
    const int a = idx >> 6;
    const int c = idx & 63;
    float a0 = 0.f, a1 = 0.f, a2 = 0.f, a3 = 0.f;
    #pragma unroll
    for (int d = 0; d < ND; d += 4) {
        a0 = fmaf(swu[(d + 0) * ND + a], swi[(d + 0) * ND + c], a0);
        a1 = fmaf(swu[(d + 1) * ND + a], swi[(d + 1) * ND + c], a1);
        a2 = fmaf(swu[(d + 2) * ND + a], swi[(d + 2) * ND + c], a2);
        a3 = fmaf(swu[(d + 3) * ND + a], swi[(d + 3) * ND + c], a3);
    }
    g_M[idx] = (a0 + a1) + (a2 + a3);

    if (blockIdx.x == 0 && tid < ND) {
        const int j = tid;
        float c1 = 0.0f, c2 = 0.0f;
        #pragma unroll 8
        for (int d = 0; d < ND; d++) {
            c1 = fmaf(swi[d * ND + j], bu[d], c1);
            c2 = fmaf(swu[d * ND + j], bi[d], c2);
        }
        g_cpe[j] = c1;
        g_cue[j] = c2;
        if (j == 0) {
            float s = 0.0f;
            #pragma unroll 8
            for (int d = 0; d < ND; d++) s = fmaf(bu[d], bi[d], s);
            g_c0 = s;
        }
    }
}

// ---------------------------------------------------------------------------
// Fused kernel args
// ---------------------------------------------------------------------------
struct FusedArgs {
    const int*   users;
    const int*   pos_items;
    const int*   neg_items;
    const float* rpkms;
    const float* user_emb;  long nu;
    const float* item_emb;  long ni;
    const float* beta_uD;
    const float* beta_iD;
    const int*   ii_nbr;
    const float* ii_con;
    const float* sp[8]; int sn[8];
    float* out;
};

// ---------------------------------------------------------------------------
// norm slice over 128 stream threads: __ldcs, 4 accumulators
// ---------------------------------------------------------------------------
__device__ __forceinline__ float norm_slice_128(const FusedArgs& a) {
    float acc0 = 0.0f, acc1 = 0.0f, acc2 = 0.0f, acc3 = 0.0f;
    const size_t tg = (size_t)blockIdx.x * 128 + threadIdx.x;
    const size_t stride = (size_t)gridDim.x * 128;

    const float4* pu = (const float4*)a.user_emb;
    const size_t mu = (size_t)a.nu >> 2;
    size_t i = tg;
    for (; i + 3 * stride < mu; i += 4 * stride) {
        float4 v0 = __ldcs(pu + i);
        float4 v1 = __ldcs(pu + i + stride);
        float4 v2 = __ldcs(pu + i + 2 * stride);
        float4 v3 = __ldcs(pu + i + 3 * stride);
        acc0 += v0.x*v0.x + v0.y*v0.y + v0.z*v0.z + v0.w*v0.w;
        acc1 += v1.x*v1.x + v1.y*v1.y + v1.z*v1.z + v1.w*v1.w;
        acc2 += v2.x*v2.x + v2.y*v2.y + v2.z*v2.z + v2.w*v2.w;
        acc3 += v3.x*v3.x + v3.y*v3.y + v3.z*v3.z + v3.w*v3.w;
    }
    for (; i < mu; i += stride) {
        float4 v = __ldcs(pu + i);
        acc0 += v.x*v.x + v.y*v.y + v.z*v.z + v.w*v.w;
    }
    const float4* pi = (const float4*)a.item_emb;
    const size_t mi = (size_t)a.ni >> 2;
    i = tg;
    for (; i + 3 * stride < mi; i += 4 * stride) {
        float4 v0 = __ldcs(pi + i);
        float4 v1 = __ldcs(pi + i + stride);
        float4 v2 = __ldcs(pi + i + 2 * stride);
        float4 v3 = __ldcs(pi + i + 3 * stride);
        acc0 += v0.x*v0.x + v0.y*v0.y + v0.z*v0.z + v0.w*v0.w;
        acc1 += v1.x*v1.x + v1.y*v1.y + v1.z*v1.z + v1.w*v1.w;
        acc2 += v2.x*v2.x + v2.y*v2.y + v2.z*v2.z + v2.w*v2.w;
        acc3 += v3.x*v3.x + v3.y*v3.y + v3.z*v3.z + v3.w*v3.w;
    }
    for (; i < mi; i += stride) {
        float4 v = __ldcs(pi + i);
        acc0 += v.x*v.x + v.y*v.y + v.z*v.z + v.w*v.w;
    }
    if (blockIdx.x == 0) {
        #pragma unroll
        for (int j = 0; j < 8; j++) {
            const float* q = a.sp[j];
            const int n = a.sn[j];
            for (int k = threadIdx.x; k < n; k += 128) {
                float v = q[k];
                acc0 += v * v;
            }
        }
    }
    return (acc0 + acc1) + (acc2 + acc3);
}

// ---------------------------------------------------------------------------
// Fused kernel: warp-specialized.
//  warps 0-3 : norm stream (no dependency on ue/pe preload)
//  warps 4-7 : gathers + dots + matvec + pos + mse (named barrier 1, 128 thr)
// ---------------------------------------------------------------------------
__global__ void __launch_bounds__(256, 5)
fused_kernel(FusedArgs a) {
    const int b    = blockIdx.x;
    const int tid  = threadIdx.x;
    const int lane = tid & 31;
    const int warp = tid >> 5;

    __shared__ float s_ue[ND];
    __shared__ float s_pe[ND];
    __shared__ float s_t[ND];
    __shared__ float sN[4], sI[4];
    __shared__ float sPosLoss, sMse;
    __shared__ float sNorm[4];
    __shared__ bool  sLast;

    if (warp < 4) {
        // ================= STREAM WARPS =================
        float nacc = norm_slice_128(a);
        nacc = bfly(nacc);
        if (lane == 0) sNorm[warp] = nacc;
    } else {
        // ================= GATHER WARPS =================
        const int gw = warp - 4;            // 0..3
        const int wg = tid - 128;           // 0..127
        const int lane8 = lane & 7;
        const int grp   = lane >> 3;

        const int u = __ldg(a.users + b);
        const int p = __ldg(a.pos_items + b);

        if (wg < ND)      s_ue[wg]      = __ldg(a.user_emb + (size_t)u * ND + wg);
        else              s_pe[wg - ND] = __ldg(a.item_emb + (size_t)p * ND + (wg - ND));

        // coalesced prefetch while ue/pe loads are in flight
        const int*   negb = a.neg_items + (size_t)b * NNEG + gw * 32;
        const int*   nbrp = a.ii_nbr   + (size_t)p * KNBR + gw * 8;
        const float* simp = a.ii_con   + (size_t)p * KNBR + gw * 8;
        const int   myneg = __ldg(negb + lane);
        const float mybi  = __ldg(a.beta_iD + myneg);
        const int   mynbr = (lane < 8) ? __ldg(nbrp + lane) : 0;
        const float mysim = (lane < 8) ? __ldg(simp + lane) : 0.0f;
        const float bu    = __ldg(a.beta_uD + u);

        BAR_GATHER();   // s_ue / s_pe ready among gather warps

        const float4 ua = ((const float4*)s_ue)[lane8];
        const float4 ub = ((const float4*)s_ue)[8 + lane8];

        // ---- negatives: 8 slots x 4 rows, 8 lanes per row ----
        float accN = 0.0f;
        #pragma unroll
        for (int slot = 0; slot < 8; slot++) {
            const int j = __shfl_sync(FULLMASK, myneg, slot * 4 + grp);
            const float4* row = (const float4*)(a.item_emb + (size_t)j * ND);
            const float4 va = __ldg(row + lane8);
            const float4 vb = __ldg(row + 8 + lane8);
            float s = dot8(va, vb, ua, ub);
            s += __shfl_xor_sync(FULLMASK, s, 1);
            s += __shfl_xor_sync(FULLMASK, s, 2);
            s += __shfl_xor_sync(FULLMASK, s, 4);
            const float bi = __shfl_sync(FULLMASK, mybi, slot * 4 + grp);
            if (lane8 == 0)
                accN += fmaf(bu, bi, W3c) * softplusf(s);
        }

        // ---- neighbors: 2 slots x 4 rows ----
        float accI = 0.0f;
        #pragma unroll
        for (int slot = 0; slot < 2; slot++) {
            const int j = __shfl_sync(FULLMASK, mynbr, slot * 4 + grp);
            const float4* row = (const float4*)(a.item_emb + (size_t)j * ND);
            const float4 va = __ldg(row + lane8);
            const float4 vb = __ldg(row + 8 + lane8);
            float s = dot8(va, vb, ua, ub);
            s += __shfl_xor_sync(FULLMASK, s, 1);
            s += __shfl_xor_sync(FULLMASK, s, 2);
            s += __shfl_xor_sync(FULLMASK, s, 4);
            const float c = __shfl_sync(FULLMASK, mysim, slot * 4 + grp);
            if (lane8 == 0)
                accI += c * softplusf(-s);
        }

        accN = bfly(accN);
        accI = bfly(accI);
        if (lane == 0) { sN[gw] = accN; sI[gw] = accI; }

        // ---- matvec (warps 6-7: 64 threads, coalesced g_M rows) ----
        if (warp >= 6) {
            const int d = tid & 63;
            float acc = g_cpe[d];
            #pragma unroll 16
            for (int k = 0; k < ND; k++)
                acc = fmaf(s_ue[k], g_M[k * ND + d], acc);
            s_t[d] = acc;
        }

        // ---- positive score (warp 4) ----
        if (warp == 4) {
            const float4 pa = ((const float4*)s_pe)[lane8];
            const float4 pb = ((const float4*)s_pe)[8 + lane8];
            float s = dot8(pa, pb, ua, ub);
            s += __shfl_xor_sync(FULLMASK, s, 1);
            s += __shfl_xor_sync(FULLMASK, s, 2);
            s += __shfl_xor_sync(FULLMASK, s, 4);
            if (lane == 0) {
                const float bip = __ldg(a.beta_iD + p);
                sPosLoss = fmaf(bu, bip, W1c) * softplusf(-s);
            }
        }

        BAR_GATHER();   // s_t ready

        // ---- mse (warp 5) ----
        if (warp == 5) {
            float v = s_t[2*lane] * s_pe[2*lane] + s_t[2*lane+1] * s_pe[2*lane+1]
                    + g_cue[2*lane] * s_ue[2*lane] + g_cue[2*lane+1] * s_ue[2*lane+1];
            v = bfly(v);
            if (lane == 0) {
                const float pred = v + g_c0;
                const float dlt = pred - __ldg(a.rpkms + b);
                sMse = dlt * dlt;
            }
        }
    }

    __syncthreads();

    if (tid == 0) {
        float sn = sN[0] + sN[1] + sN[2] + sN[3];
        float si = sI[0] + sI[1] + sI[2] + sI[3];
        g_lossL[b] = sPosLoss + NEG_WEIGHTc * (sn * (1.0f / NNEG));
        g_lossI[b] = si;
        g_mseP[b]  = sMse;
        g_norm_partial[b] = sNorm[0] + sNorm[1] + sNorm[2] + sNorm[3];
    }

    // ---- last-block finalize ----
    __threadfence();
    if (tid == 0) sLast = (atomicAdd(&g_done, 1u) == (unsigned)(NB - 1));
    __syncthreads();
    if (!sLast) return;
    __threadfence();

    double aL = 0.0, aI = 0.0, aM = 0.0, aN = 0.0;
    for (int i = tid; i < NB; i += 256) {
        aL += (double)g_lossL[i];
        aI += (double)g_lossI[i];
        aM += (double)g_mseP[i];
        aN += (double)g_norm_partial[i];
    }
    __shared__ double rL[256], rI[256], rM[256], rN[256];
    rL[tid] = aL; rI[tid] = aI; rM[tid] = aM; rN[tid] = aN;
    __syncthreads();
    for (int o = 128; o; o >>= 1) {
        if (tid < o) {
            rL[tid] += rL[tid + o];
            rI[tid] += rI[tid + o];
            rM[tid] += rM[tid + o];
            rN[tid] += rN[tid + o];
        }
        __syncthreads();
    }
    if (tid == 0) {
        const double lossL = rL[0] / (double)NB;
        const double lossI = rI[0] * ((double)LAMBDAc / ((double)NB * (double)KNBR));
        const double mse   = rM[0] / (double)NB;
        const double norm  = rN[0] * 0.5 * (double)GAMMAc;
        float* out = a.out;
        out[0] = (float)(lossL + lossI + mse + norm);
        out[1] = (float)lossL;
        out[2] = (float)lossI;
        out[3] = 0.0f;
        out[4] = (float)mse;
        out[5] = (float)norm;
    }
}

// ---------------------------------------------------------------------------
// Launch
// ---------------------------------------------------------------------------
extern "C" void kernel_launch(void* const* d_in, const int* in_sizes, int n_in,
                              void* d_out, int out_size) {
    FusedArgs a;
    a.users     = (const int*)d_in[0];
    a.pos_items = (const int*)d_in[1];
    a.neg_items = (const int*)d_in[2];
    a.rpkms     = (const float*)d_in[3];
    a.user_emb  = (const float*)d_in[4];  a.nu = in_sizes[4];
    a.item_emb  = (const float*)d_in[5];  a.ni = in_sizes[5];
    a.beta_uD   = (const float*)d_in[6];
    a.beta_iD   = (const float*)d_in[7];
    a.ii_nbr    = (const int*)d_in[8];
    a.ii_con    = (const float*)d_in[9];
    const float* mse_u_w = (const float*)d_in[10];
    const float* mse_u_b = (const float*)d_in[11];
    const float* mse_i_w = (const float*)d_in[12];
    const float* mse_i_b = (const float*)d_in[13];
    a.sp[0] = mse_u_w;               a.sn[0] = in_sizes[10];
    a.sp[1] = mse_u_b;               a.sn[1] = in_sizes[11];
    a.sp[2] = mse_i_w;               a.sn[2] = in_sizes[12];
    a.sp[3] = mse_i_b;               a.sn[3] = in_sizes[13];
    a.sp[4] = (const float*)d_in[14]; a.sn[4] = in_sizes[14];
    a.sp[5] = (const float*)d_in[15]; a.sn[5] = in_sizes[15];
    a.sp[6] = (const float*)d_in[16]; a.sn[6] = in_sizes[16];
    a.sp[7] = (const float*)d_in[17]; a.sn[7] = in_sizes[17];
    a.out   = (float*)d_out;

    precompute_kernel<<<16, 256>>>(mse_u_w, mse_u_b, mse_i_w, mse_i_b);
    fused_kernel<<<NB, 256>>>(a);
}